// round 7
// baseline (speedup 1.0000x reference)
#include <cuda_runtime.h>
#include <cuda_fp16.h>
#include <math.h>

// ============================================================================
// PermInvariantQNN — exact piecewise-linear collapse of the scalar encoder.
// Round 7: decoder rebuilt as 2-threads-per-row with shfl_xor exchange
//          (halves per-thread instruction count, raises occupancy).
//          Prep + encoder unchanged from R6.
// ============================================================================

#define BATCH     131072
#define NBP_MAX   512
#define NSEG_MAX  512
#define NCELL     4096
#define XLO_F     (-6.0f)
#define STEP_F    (12.0f / 4096.0f)
#define INVSTEP_F (4096.0f / 12.0f)
#define HALFCELLS 2048.0f

__device__ float          g_bp[NBP_MAX];        // sorted breakpoints, +INF padded
__device__ unsigned int   g_rec[NSEG_MAX * 6];  // [xmid f32, 5x half2(s,v)] * (1/64)
__device__ int            g_nbp;
__device__ unsigned short g_cell[NCELL];        // low15: upper-bound idx, bit15: dirty
__device__ float          g_mom[5 * BATCH];     // SoA moments scratch

// ----------------------------------------------------------------------------
// Prep A: sort + cell table. 1 block x 512 threads.
// ----------------------------------------------------------------------------
__global__ void prep_sort_kernel(const float* __restrict__ eW1, const float* __restrict__ eb1,
                                 const float* __restrict__ eW2, const float* __restrict__ eb2)
{
    __shared__ float sa[20], sb1[20], sW2[400], sb2[20];
    __shared__ float s_t[21];
    __shared__ int   s_n1, s_n;
    __shared__ float cand[512];
    __shared__ unsigned short s_lo[NCELL];

    const int tid = threadIdx.x;

    if (tid < 20)  { sa[tid] = eW1[tid]; sb1[tid] = eb1[tid]; sb2[tid] = eb2[tid]; }
    if (tid < 400) sW2[tid] = eW2[tid];
    cand[tid] = INFINITY;
    if (tid == 0) s_n = 0;
    __syncthreads();

    // phase 1: layer-1 breakpoints via warp rank-sort
    if (tid < 32) {
        float tj = INFINITY;
        if (tid < 20) {
            float a = sa[tid];
            if (a != 0.0f) {
                float t = -sb1[tid] / a;
                if (isfinite(t)) tj = t;
            }
        }
        int rnk = 0;
        #pragma unroll
        for (int j = 0; j < 32; j++) {
            float u = __shfl_sync(0xFFFFFFFFu, tj, j);
            rnk += (u < tj) || (u == tj && j < tid);
        }
        bool fin = isfinite(tj);
        if (fin) { s_t[rnk] = tj; cand[rnk] = tj; }
        unsigned m = __ballot_sync(0xFFFFFFFFu, fin);
        if (tid == 0) { s_n1 = __popc(m); atomicAdd(&s_n, __popc(m)); }
    }
    __syncthreads();
    const int n1 = s_n1;

    // phase 2: layer-2 zero crossings
    if (tid < 21 * 20) {
        int p = tid / 20, k = tid % 20;
        if (p <= n1) {
            float lo = (p == 0)  ? -INFINITY : s_t[p - 1];
            float hi = (p == n1) ?  INFINITY : s_t[p];
            float xr;
            if (n1 == 0)      xr = 0.0f;
            else if (p == 0)  xr = s_t[0] - 1.0f;
            else if (p == n1) xr = s_t[n1 - 1] + 1.0f;
            else              xr = 0.5f * (lo + hi);
            float zs = 0.0f, zi = sb2[k];
            for (int j = 0; j < 20; j++) {
                float pre = fmaf(sa[j], xr, sb1[j]);
                if (pre > 0.0f) {
                    zs = fmaf(sa[j],  sW2[j * 20 + k], zs);
                    zi = fmaf(sb1[j], sW2[j * 20 + k], zi);
                }
            }
            if (zs != 0.0f) {
                float xc = -zi / zs;
                if (isfinite(xc) && xc > lo && xc < hi) {
                    cand[20 + p * 20 + k] = xc;
                    atomicAdd(&s_n, 1);
                }
            }
        }
    }
    __syncthreads();

    // phase 3: hybrid bitonic sort (intra-warp stages via shfl)
    {
        float v = cand[tid];
        for (int k = 2; k <= 512; k <<= 1) {
            for (int j = k >> 1; j > 0; j >>= 1) {
                float u;
                if (j >= 32) {
                    cand[tid] = v; __syncthreads();
                    u = cand[tid ^ j]; __syncthreads();
                } else {
                    u = __shfl_xor_sync(0xFFFFFFFFu, v, j);
                }
                bool up = ((tid & k) == 0);
                bool keepmin = (up == ((tid & j) == 0));
                v = keepmin ? fminf(v, u) : fmaxf(v, u);
            }
        }
        cand[tid] = v;
        __syncthreads();
    }

    const int n = s_n;
    if (tid == 0) g_nbp = n;
    g_bp[tid] = cand[tid];                       // +INF padded

    // phase 4: per-cell upper-bound (balanced) + dirty bits
    for (int c = tid; c < NCELL; c += 512) {
        float left = XLO_F + (float)c * STEP_F;
        int lo = 0, hi = 512;
        while (lo < hi) {
            int mid = (lo + hi) >> 1;
            if (cand[mid] <= left) lo = mid + 1; else hi = mid;
        }
        s_lo[c] = (unsigned short)lo;
    }
    __syncthreads();
    for (int c = tid; c < NCELL; c += 512) {
        int lo = s_lo[c];
        int hi = (c == NCELL - 1) ? n : (int)s_lo[c + 1];
        g_cell[c] = (unsigned short)(lo | (hi > lo ? 0x8000 : 0));
    }
}

// ----------------------------------------------------------------------------
// Prep B: per-segment records. 4 blocks x 128 threads.
// ----------------------------------------------------------------------------
__global__ void prep_rec_kernel(const float* __restrict__ eW1, const float* __restrict__ eb1,
                                const float* __restrict__ eW2, const float* __restrict__ eb2,
                                const float* __restrict__ eW3, const float* __restrict__ eb3)
{
    __shared__ float sa[20], sb1[20], sW2[400], sb2[20], sW3[100], sb3[5];
    const int tid = threadIdx.x;
    if (tid < 20)  { sa[tid] = eW1[tid]; sb1[tid] = eb1[tid]; sb2[tid] = eb2[tid]; }
    for (int i = tid; i < 400; i += 128) sW2[i] = eW2[i];
    if (tid < 100) sW3[tid] = eW3[tid];
    if (tid < 5)   sb3[tid] = eb3[tid];
    __syncthreads();

    const int sid = blockIdx.x * 128 + tid;
    const int n   = g_nbp;
    if (sid > n) return;

    float xr;
    if (n == 0)        xr = 0.0f;
    else if (sid == 0) xr = g_bp[0] - 1.0f;
    else if (sid == n) xr = g_bp[n - 1] + 1.0f;
    else               xr = 0.5f * (g_bp[sid - 1] + g_bp[sid]);

    float ha[20], hb[20];
    #pragma unroll
    for (int j = 0; j < 20; j++) {
        float pre = fmaf(sa[j], xr, sb1[j]);
        bool act = pre > 0.0f;
        ha[j] = act ? sa[j]  : 0.0f;
        hb[j] = act ? sb1[j] : 0.0f;
    }
    float sm[5] = {0, 0, 0, 0, 0}, cm[5] = {0, 0, 0, 0, 0};
    for (int k = 0; k < 20; k++) {
        float zs = 0.0f, zi = sb2[k];
        #pragma unroll
        for (int j = 0; j < 20; j++) {
            zs = fmaf(ha[j], sW2[j * 20 + k], zs);
            zi = fmaf(hb[j], sW2[j * 20 + k], zi);
        }
        if (fmaf(zs, xr, zi) > 0.0f) {
            #pragma unroll
            for (int m = 0; m < 5; m++) {
                sm[m] = fmaf(zs, sW3[k * 5 + m], sm[m]);
                cm[m] = fmaf(zi, sW3[k * 5 + m], cm[m]);
            }
        }
    }
    unsigned int* rec = g_rec + sid * 6;
    rec[0] = __float_as_uint(xr);
    #pragma unroll
    for (int m = 0; m < 5; m++) {
        float v = fmaf(sm[m], xr, cm[m] + sb3[m]);   // f_m at xr
        __half2 h = __floats2half2_rn(sm[m] * 0.015625f, v * 0.015625f);
        rec[1 + m] = *(unsigned int*)&h;
    }
}

// ----------------------------------------------------------------------------
// Encoder kernel: 1 row/thread, clean/dirty cell lookup.
// ----------------------------------------------------------------------------
__device__ __forceinline__ int pwl_find(float x,
                                        const float* __restrict__ s_bp,
                                        const unsigned short* __restrict__ s_cell)
{
    float fc = fmaf(x, INVSTEP_F, HALFCELLS);
    int c = __float2int_rz(fc);
    c = min(max(c, 0), NCELL - 1);
    unsigned e = s_cell[c];
    int s = e & 0x7FFF;
    bool walk = (e & 0x8000u) != 0;
    if (fc < 0.0f) { s = 0; walk = true; }
    if (walk) { while (s_bp[s] <= x) ++s; }      // +INF padding terminates
    return s;
}

__device__ __forceinline__ void pwl_acc(float x, const uint2* __restrict__ p,
                                        float acc[5])
{
    uint2 r0 = p[0], r1 = p[1], r2 = p[2];
    float dx = x - __uint_as_float(r0.x);
    float2 m0 = __half22float2(*(__half2*)&r0.y);
    float2 m1 = __half22float2(*(__half2*)&r1.x);
    float2 m2 = __half22float2(*(__half2*)&r1.y);
    float2 m3 = __half22float2(*(__half2*)&r2.x);
    float2 m4 = __half22float2(*(__half2*)&r2.y);
    acc[0] += fmaf(m0.x, dx, m0.y);
    acc[1] += fmaf(m1.x, dx, m1.y);
    acc[2] += fmaf(m2.x, dx, m2.y);
    acc[3] += fmaf(m3.x, dx, m3.y);
    acc[4] += fmaf(m4.x, dx, m4.y);
}

__global__ __launch_bounds__(128, 9) void enc_kernel(const float* __restrict__ inv)
{
    __shared__ __align__(16) float          s_bp[NBP_MAX];       // 2 KB
    __shared__ __align__(16) unsigned int   s_rec[NSEG_MAX * 6]; // 12 KB
    __shared__ __align__(16) unsigned short s_cell[NCELL];       // 8 KB

    const int tid = threadIdx.x;

    {
        const uint4* src = (const uint4*)g_rec;
        uint4* dst = (uint4*)s_rec;
        #pragma unroll
        for (int i = tid; i < NSEG_MAX * 6 / 4; i += 128) dst[i] = src[i];
        ((float4*)s_bp)[tid] = ((const float4*)g_bp)[tid];
        const uint4* csrc = (const uint4*)g_cell;
        uint4* cdst = (uint4*)s_cell;
        #pragma unroll
        for (int i = tid; i < NCELL / 8; i += 128) cdst[i] = csrc[i];
    }
    __syncthreads();

    const int r = blockIdx.x * 128 + tid;
    const uint2* rec = (const uint2*)s_rec;

    float acc[5] = {0, 0, 0, 0, 0};
    const float4* p0 = (const float4*)inv + (size_t)r * 16;
    #pragma unroll 4
    for (int i = 0; i < 16; i++) {
        float4 a = p0[i];
        int sA = pwl_find(a.x, s_bp, s_cell);
        int sB = pwl_find(a.y, s_bp, s_cell);
        int sC = pwl_find(a.z, s_bp, s_cell);
        int sD = pwl_find(a.w, s_bp, s_cell);
        pwl_acc(a.x, rec + sA * 3, acc);
        pwl_acc(a.y, rec + sB * 3, acc);
        pwl_acc(a.z, rec + sC * 3, acc);
        pwl_acc(a.w, rec + sD * 3, acc);
    }

    #pragma unroll
    for (int m = 0; m < 5; m++) g_mom[m * BATCH + r] = acc[m];
}

// ----------------------------------------------------------------------------
// Decoder kernel: 2 threads per row, shfl_xor half-exchange.
//   even lane -> neurons 0..9, odd lane -> neurons 10..19 (layers 1 & 2)
// ----------------------------------------------------------------------------
__global__ __launch_bounds__(256) void dec_kernel(
    const float* __restrict__ noninv,
    const float* __restrict__ dW1,  const float* __restrict__ db1,
    const float* __restrict__ dW2,  const float* __restrict__ db2,
    const float* __restrict__ dW3,  const float* __restrict__ db3,
    float* __restrict__ out)
{
    __shared__ __align__(16) float s_dw[784]; // dW1[260] db1[20] dW2[400] db2[20] dW3[80] db3[4]
    const int tid = threadIdx.x;

    for (int i = tid; i < 260; i += 256) s_dw[i] = dW1[i];
    if (tid < 20) s_dw[260 + tid] = db1[tid];
    for (int i = tid; i < 400; i += 256) s_dw[280 + i] = dW2[i];
    if (tid < 20) s_dw[680 + tid] = db2[tid];
    if (tid < 80) s_dw[700 + tid] = dW3[tid];
    if (tid < 4)  s_dw[780 + tid] = db3[tid];
    __syncthreads();

    const int gtid = blockIdx.x * 256 + tid;
    const int r    = gtid >> 1;          // row
    const int half = gtid & 1;           // 0: neurons 0..9, 1: neurons 10..19
    const int nb   = half * 10;          // neuron base

    // ---- gather cat[13] (both halves read; L1-hit broadcast) ----
    float cat[13];
    #pragma unroll
    for (int m = 0; m < 5; m++) cat[m] = g_mom[m * BATCH + r];
    {
        float4 u0 = *(const float4*)(noninv + (size_t)r * 8);
        float4 u1 = *(const float4*)(noninv + (size_t)r * 8 + 4);
        cat[5] = u0.x; cat[6] = u0.y; cat[7]  = u0.z; cat[8]  = u0.w;
        cat[9] = u1.x; cat[10] = u1.y; cat[11] = u1.z; cat[12] = u1.w;
    }

    // ---- layer 1: my 10 neurons ----
    float myh[10];
    #pragma unroll
    for (int i = 0; i < 10; i += 2) {
        float2 z = *(const float2*)&s_dw[260 + nb + i];
        #pragma unroll
        for (int c = 0; c < 13; c++) {
            float2 w = *(const float2*)&s_dw[c * 20 + nb + i];
            z.x = fmaf(cat[c], w.x, z.x);
            z.y = fmaf(cat[c], w.y, z.y);
        }
        myh[i]     = fmaxf(z.x, 0.0f);
        myh[i + 1] = fmaxf(z.y, 0.0f);
    }

    // ---- exchange: build full h[20] ----
    float hall[20];
    #pragma unroll
    for (int i = 0; i < 10; i++) {
        float o = __shfl_xor_sync(0xFFFFFFFFu, myh[i], 1);
        hall[i]      = half ? o      : myh[i];
        hall[10 + i] = half ? myh[i] : o;
    }

    // ---- layer 2: my 10 neurons ----
    float g[10];
    #pragma unroll
    for (int i = 0; i < 10; i += 2) {
        float2 z = *(const float2*)&s_dw[680 + nb + i];
        #pragma unroll
        for (int j = 0; j < 20; j++) {
            float2 w = *(const float2*)&s_dw[280 + j * 20 + nb + i];
            z.x = fmaf(hall[j], w.x, z.x);
            z.y = fmaf(hall[j], w.y, z.y);
        }
        g[i]     = fmaxf(z.x, 0.0f);
        g[i + 1] = fmaxf(z.y, 0.0f);
    }

    // ---- layer 3: partial over my 10 g's, shfl-reduce, even lane writes ----
    float4 o = half ? make_float4(0.f, 0.f, 0.f, 0.f)
                    : *(const float4*)&s_dw[780];
    #pragma unroll
    for (int i = 0; i < 10; i++) {
        float4 w = *(const float4*)&s_dw[700 + (nb + i) * 4];
        o.x = fmaf(g[i], w.x, o.x);
        o.y = fmaf(g[i], w.y, o.y);
        o.z = fmaf(g[i], w.z, o.z);
        o.w = fmaf(g[i], w.w, o.w);
    }
    o.x += __shfl_xor_sync(0xFFFFFFFFu, o.x, 1);
    o.y += __shfl_xor_sync(0xFFFFFFFFu, o.y, 1);
    o.z += __shfl_xor_sync(0xFFFFFFFFu, o.z, 1);
    o.w += __shfl_xor_sync(0xFFFFFFFFu, o.w, 1);
    if (half == 0)
        *(float4*)(out + (size_t)r * 4) = o;
}

// ----------------------------------------------------------------------------
extern "C" void kernel_launch(void* const* d_in, const int* in_sizes, int n_in,
                              void* d_out, int out_size)
{
    (void)in_sizes; (void)n_in; (void)out_size;
    const float* invar  = (const float*)d_in[0];
    const float* noninv = (const float*)d_in[1];
    const float* eW1 = (const float*)d_in[2];
    const float* eb1 = (const float*)d_in[3];
    const float* eW2 = (const float*)d_in[4];
    const float* eb2 = (const float*)d_in[5];
    const float* eW3 = (const float*)d_in[6];
    const float* eb3 = (const float*)d_in[7];
    const float* dW1 = (const float*)d_in[8];
    const float* db1 = (const float*)d_in[9];
    const float* dW2 = (const float*)d_in[10];
    const float* db2 = (const float*)d_in[11];
    const float* dW3 = (const float*)d_in[12];
    const float* db3 = (const float*)d_in[13];

    prep_sort_kernel<<<1, 512>>>(eW1, eb1, eW2, eb2);
    prep_rec_kernel<<<4, 128>>>(eW1, eb1, eW2, eb2, eW3, eb3);
    enc_kernel<<<BATCH / 128, 128>>>(invar);
    dec_kernel<<<BATCH / 128, 256>>>(noninv, dW1, db1, dW2, db2, dW3, db3,
                                     (float*)d_out);
}

// round 8
// speedup vs baseline: 1.0471x; 1.0471x over previous
#include <cuda_runtime.h>
#include <cuda_fp16.h>
#include <math.h>

// ============================================================================
// PermInvariantQNN — exact piecewise-linear collapse of the scalar encoder.
// Round 8: encoder+decoder fused into ONE kernel. Thread-pair per row:
//          each thread evaluates 32/64 inputs (PWL), shfl-combines moments,
//          then the R7 half-split decoder (10 neurons/thread) — no g_mom
//          scratch, no dec launch.
// ============================================================================

#define BATCH     131072
#define NBP_MAX   512
#define NSEG_MAX  512
#define NCELL     4096
#define XLO_F     (-6.0f)
#define STEP_F    (12.0f / 4096.0f)
#define INVSTEP_F (4096.0f / 12.0f)
#define HALFCELLS 2048.0f

__device__ float          g_bp[NBP_MAX];        // sorted breakpoints, +INF padded
__device__ unsigned int   g_rec[NSEG_MAX * 6];  // [xmid f32, 5x half2(s,v)] * (1/64)
__device__ int            g_nbp;
__device__ unsigned short g_cell[NCELL];        // low15: upper-bound idx, bit15: dirty

// ----------------------------------------------------------------------------
// Prep A: sort + cell table. 1 block x 512 threads.
// ----------------------------------------------------------------------------
__global__ void prep_sort_kernel(const float* __restrict__ eW1, const float* __restrict__ eb1,
                                 const float* __restrict__ eW2, const float* __restrict__ eb2)
{
    __shared__ float sa[20], sb1[20], sW2[400], sb2[20];
    __shared__ float s_t[21];
    __shared__ int   s_n1, s_n;
    __shared__ float cand[512];
    __shared__ unsigned short s_lo[NCELL];

    const int tid = threadIdx.x;

    if (tid < 20)  { sa[tid] = eW1[tid]; sb1[tid] = eb1[tid]; sb2[tid] = eb2[tid]; }
    if (tid < 400) sW2[tid] = eW2[tid];
    cand[tid] = INFINITY;
    if (tid == 0) s_n = 0;
    __syncthreads();

    // phase 1: layer-1 breakpoints via warp rank-sort
    if (tid < 32) {
        float tj = INFINITY;
        if (tid < 20) {
            float a = sa[tid];
            if (a != 0.0f) {
                float t = -sb1[tid] / a;
                if (isfinite(t)) tj = t;
            }
        }
        int rnk = 0;
        #pragma unroll
        for (int j = 0; j < 32; j++) {
            float u = __shfl_sync(0xFFFFFFFFu, tj, j);
            rnk += (u < tj) || (u == tj && j < tid);
        }
        bool fin = isfinite(tj);
        if (fin) { s_t[rnk] = tj; cand[rnk] = tj; }
        unsigned m = __ballot_sync(0xFFFFFFFFu, fin);
        if (tid == 0) { s_n1 = __popc(m); atomicAdd(&s_n, __popc(m)); }
    }
    __syncthreads();
    const int n1 = s_n1;

    // phase 2: layer-2 zero crossings
    if (tid < 21 * 20) {
        int p = tid / 20, k = tid % 20;
        if (p <= n1) {
            float lo = (p == 0)  ? -INFINITY : s_t[p - 1];
            float hi = (p == n1) ?  INFINITY : s_t[p];
            float xr;
            if (n1 == 0)      xr = 0.0f;
            else if (p == 0)  xr = s_t[0] - 1.0f;
            else if (p == n1) xr = s_t[n1 - 1] + 1.0f;
            else              xr = 0.5f * (lo + hi);
            float zs = 0.0f, zi = sb2[k];
            for (int j = 0; j < 20; j++) {
                float pre = fmaf(sa[j], xr, sb1[j]);
                if (pre > 0.0f) {
                    zs = fmaf(sa[j],  sW2[j * 20 + k], zs);
                    zi = fmaf(sb1[j], sW2[j * 20 + k], zi);
                }
            }
            if (zs != 0.0f) {
                float xc = -zi / zs;
                if (isfinite(xc) && xc > lo && xc < hi) {
                    cand[20 + p * 20 + k] = xc;
                    atomicAdd(&s_n, 1);
                }
            }
        }
    }
    __syncthreads();

    // phase 3: hybrid bitonic sort (intra-warp stages via shfl)
    {
        float v = cand[tid];
        for (int k = 2; k <= 512; k <<= 1) {
            for (int j = k >> 1; j > 0; j >>= 1) {
                float u;
                if (j >= 32) {
                    cand[tid] = v; __syncthreads();
                    u = cand[tid ^ j]; __syncthreads();
                } else {
                    u = __shfl_xor_sync(0xFFFFFFFFu, v, j);
                }
                bool up = ((tid & k) == 0);
                bool keepmin = (up == ((tid & j) == 0));
                v = keepmin ? fminf(v, u) : fmaxf(v, u);
            }
        }
        cand[tid] = v;
        __syncthreads();
    }

    const int n = s_n;
    if (tid == 0) g_nbp = n;
    g_bp[tid] = cand[tid];                       // +INF padded

    // phase 4: per-cell upper-bound (balanced) + dirty bits
    for (int c = tid; c < NCELL; c += 512) {
        float left = XLO_F + (float)c * STEP_F;
        int lo = 0, hi = 512;
        while (lo < hi) {
            int mid = (lo + hi) >> 1;
            if (cand[mid] <= left) lo = mid + 1; else hi = mid;
        }
        s_lo[c] = (unsigned short)lo;
    }
    __syncthreads();
    for (int c = tid; c < NCELL; c += 512) {
        int lo = s_lo[c];
        int hi = (c == NCELL - 1) ? n : (int)s_lo[c + 1];
        g_cell[c] = (unsigned short)(lo | (hi > lo ? 0x8000 : 0));
    }
}

// ----------------------------------------------------------------------------
// Prep B: per-segment records. 4 blocks x 128 threads.
// ----------------------------------------------------------------------------
__global__ void prep_rec_kernel(const float* __restrict__ eW1, const float* __restrict__ eb1,
                                const float* __restrict__ eW2, const float* __restrict__ eb2,
                                const float* __restrict__ eW3, const float* __restrict__ eb3)
{
    __shared__ float sa[20], sb1[20], sW2[400], sb2[20], sW3[100], sb3[5];
    const int tid = threadIdx.x;
    if (tid < 20)  { sa[tid] = eW1[tid]; sb1[tid] = eb1[tid]; sb2[tid] = eb2[tid]; }
    for (int i = tid; i < 400; i += 128) sW2[i] = eW2[i];
    if (tid < 100) sW3[tid] = eW3[tid];
    if (tid < 5)   sb3[tid] = eb3[tid];
    __syncthreads();

    const int sid = blockIdx.x * 128 + tid;
    const int n   = g_nbp;
    if (sid > n) return;

    float xr;
    if (n == 0)        xr = 0.0f;
    else if (sid == 0) xr = g_bp[0] - 1.0f;
    else if (sid == n) xr = g_bp[n - 1] + 1.0f;
    else               xr = 0.5f * (g_bp[sid - 1] + g_bp[sid]);

    float ha[20], hb[20];
    #pragma unroll
    for (int j = 0; j < 20; j++) {
        float pre = fmaf(sa[j], xr, sb1[j]);
        bool act = pre > 0.0f;
        ha[j] = act ? sa[j]  : 0.0f;
        hb[j] = act ? sb1[j] : 0.0f;
    }
    float sm[5] = {0, 0, 0, 0, 0}, cm[5] = {0, 0, 0, 0, 0};
    for (int k = 0; k < 20; k++) {
        float zs = 0.0f, zi = sb2[k];
        #pragma unroll
        for (int j = 0; j < 20; j++) {
            zs = fmaf(ha[j], sW2[j * 20 + k], zs);
            zi = fmaf(hb[j], sW2[j * 20 + k], zi);
        }
        if (fmaf(zs, xr, zi) > 0.0f) {
            #pragma unroll
            for (int m = 0; m < 5; m++) {
                sm[m] = fmaf(zs, sW3[k * 5 + m], sm[m]);
                cm[m] = fmaf(zi, sW3[k * 5 + m], cm[m]);
            }
        }
    }
    unsigned int* rec = g_rec + sid * 6;
    rec[0] = __float_as_uint(xr);
    #pragma unroll
    for (int m = 0; m < 5; m++) {
        float v = fmaf(sm[m], xr, cm[m] + sb3[m]);   // f_m at xr
        __half2 h = __floats2half2_rn(sm[m] * 0.015625f, v * 0.015625f);
        rec[1 + m] = *(unsigned int*)&h;
    }
}

// ----------------------------------------------------------------------------
// Fused encoder+decoder: thread-pair per row.
// ----------------------------------------------------------------------------
__device__ __forceinline__ int pwl_find(float x,
                                        const float* __restrict__ s_bp,
                                        const unsigned short* __restrict__ s_cell)
{
    float fc = fmaf(x, INVSTEP_F, HALFCELLS);
    int c = __float2int_rz(fc);
    c = min(max(c, 0), NCELL - 1);
    unsigned e = s_cell[c];
    int s = e & 0x7FFF;
    bool walk = (e & 0x8000u) != 0;
    if (fc < 0.0f) { s = 0; walk = true; }
    if (walk) { while (s_bp[s] <= x) ++s; }      // +INF padding terminates
    return s;
}

__device__ __forceinline__ void pwl_acc(float x, const uint2* __restrict__ p,
                                        float acc[5])
{
    uint2 r0 = p[0], r1 = p[1], r2 = p[2];
    float dx = x - __uint_as_float(r0.x);
    float2 m0 = __half22float2(*(__half2*)&r0.y);
    float2 m1 = __half22float2(*(__half2*)&r1.x);
    float2 m2 = __half22float2(*(__half2*)&r1.y);
    float2 m3 = __half22float2(*(__half2*)&r2.x);
    float2 m4 = __half22float2(*(__half2*)&r2.y);
    acc[0] += fmaf(m0.x, dx, m0.y);
    acc[1] += fmaf(m1.x, dx, m1.y);
    acc[2] += fmaf(m2.x, dx, m2.y);
    acc[3] += fmaf(m3.x, dx, m3.y);
    acc[4] += fmaf(m4.x, dx, m4.y);
}

__global__ __launch_bounds__(256, 4) void fused_kernel(
    const float* __restrict__ inv,  const float* __restrict__ noninv,
    const float* __restrict__ dW1,  const float* __restrict__ db1,
    const float* __restrict__ dW2,  const float* __restrict__ db2,
    const float* __restrict__ dW3,  const float* __restrict__ db3,
    float* __restrict__ out)
{
    __shared__ __align__(16) float          s_bp[NBP_MAX];       // 2 KB
    __shared__ __align__(16) unsigned int   s_rec[NSEG_MAX * 6]; // 12 KB
    __shared__ __align__(16) unsigned short s_cell[NCELL];       // 8 KB
    __shared__ __align__(16) float          s_dw[784];           // 3.1 KB

    const int tid = threadIdx.x;

    {
        const uint4* src = (const uint4*)g_rec;
        uint4* dst = (uint4*)s_rec;
        #pragma unroll
        for (int i = tid; i < NSEG_MAX * 6 / 4; i += 256) dst[i] = src[i];
        ((float2*)s_bp)[tid] = ((const float2*)g_bp)[tid];
        const uint4* csrc = (const uint4*)g_cell;
        uint4* cdst = (uint4*)s_cell;
        #pragma unroll
        for (int i = tid; i < NCELL / 8; i += 256) cdst[i] = csrc[i];
        for (int i = tid; i < 260; i += 256) s_dw[i] = dW1[i];
        if (tid < 20) s_dw[260 + tid] = db1[tid];
        for (int i = tid; i < 400; i += 256) s_dw[280 + i] = dW2[i];
        if (tid < 20) s_dw[680 + tid] = db2[tid];
        if (tid < 80) s_dw[700 + tid] = dW3[tid];
        if (tid < 4)  s_dw[780 + tid] = db3[tid];
    }
    __syncthreads();

    const int gtid = blockIdx.x * 256 + tid;
    const int r    = gtid >> 1;          // row
    const int half = gtid & 1;           // 0/1: input half + neuron half
    const int nb   = half * 10;          // neuron base
    const uint2* rec = (const uint2*)s_rec;

    // -------- encoder: my 32 of the row's 64 inputs --------
    float acc[5] = {0, 0, 0, 0, 0};
    const float4* p0 = (const float4*)inv + (size_t)r * 16 + half * 8;
    #pragma unroll 4
    for (int i = 0; i < 8; i++) {
        float4 a = p0[i];
        int sA = pwl_find(a.x, s_bp, s_cell);
        int sB = pwl_find(a.y, s_bp, s_cell);
        int sC = pwl_find(a.z, s_bp, s_cell);
        int sD = pwl_find(a.w, s_bp, s_cell);
        pwl_acc(a.x, rec + sA * 3, acc);
        pwl_acc(a.y, rec + sB * 3, acc);
        pwl_acc(a.z, rec + sC * 3, acc);
        pwl_acc(a.w, rec + sD * 3, acc);
    }

    // -------- combine moments across the pair; build cat[13] --------
    float cat[13];
    #pragma unroll
    for (int m = 0; m < 5; m++)
        cat[m] = acc[m] + __shfl_xor_sync(0xFFFFFFFFu, acc[m], 1);
    {
        float4 u0 = *(const float4*)(noninv + (size_t)r * 8);
        float4 u1 = *(const float4*)(noninv + (size_t)r * 8 + 4);
        cat[5] = u0.x; cat[6] = u0.y; cat[7]  = u0.z; cat[8]  = u0.w;
        cat[9] = u1.x; cat[10] = u1.y; cat[11] = u1.z; cat[12] = u1.w;
    }

    // -------- decoder layer 1: my 10 neurons --------
    float myh[10];
    #pragma unroll
    for (int i = 0; i < 10; i += 2) {
        float2 z = *(const float2*)&s_dw[260 + nb + i];
        #pragma unroll
        for (int c = 0; c < 13; c++) {
            float2 w = *(const float2*)&s_dw[c * 20 + nb + i];
            z.x = fmaf(cat[c], w.x, z.x);
            z.y = fmaf(cat[c], w.y, z.y);
        }
        myh[i]     = fmaxf(z.x, 0.0f);
        myh[i + 1] = fmaxf(z.y, 0.0f);
    }

    // -------- exchange h halves --------
    float hall[20];
    #pragma unroll
    for (int i = 0; i < 10; i++) {
        float o = __shfl_xor_sync(0xFFFFFFFFu, myh[i], 1);
        hall[i]      = half ? o      : myh[i];
        hall[10 + i] = half ? myh[i] : o;
    }

    // -------- decoder layer 2: my 10 neurons --------
    float g[10];
    #pragma unroll
    for (int i = 0; i < 10; i += 2) {
        float2 z = *(const float2*)&s_dw[680 + nb + i];
        #pragma unroll
        for (int j = 0; j < 20; j++) {
            float2 w = *(const float2*)&s_dw[280 + j * 20 + nb + i];
            z.x = fmaf(hall[j], w.x, z.x);
            z.y = fmaf(hall[j], w.y, z.y);
        }
        g[i]     = fmaxf(z.x, 0.0f);
        g[i + 1] = fmaxf(z.y, 0.0f);
    }

    // -------- decoder layer 3: partial + shfl reduce --------
    float4 o = half ? make_float4(0.f, 0.f, 0.f, 0.f)
                    : *(const float4*)&s_dw[780];
    #pragma unroll
    for (int i = 0; i < 10; i++) {
        float4 w = *(const float4*)&s_dw[700 + (nb + i) * 4];
        o.x = fmaf(g[i], w.x, o.x);
        o.y = fmaf(g[i], w.y, o.y);
        o.z = fmaf(g[i], w.z, o.z);
        o.w = fmaf(g[i], w.w, o.w);
    }
    o.x += __shfl_xor_sync(0xFFFFFFFFu, o.x, 1);
    o.y += __shfl_xor_sync(0xFFFFFFFFu, o.y, 1);
    o.z += __shfl_xor_sync(0xFFFFFFFFu, o.z, 1);
    o.w += __shfl_xor_sync(0xFFFFFFFFu, o.w, 1);
    if (half == 0)
        *(float4*)(out + (size_t)r * 4) = o;
}

// ----------------------------------------------------------------------------
extern "C" void kernel_launch(void* const* d_in, const int* in_sizes, int n_in,
                              void* d_out, int out_size)
{
    (void)in_sizes; (void)n_in; (void)out_size;
    const float* invar  = (const float*)d_in[0];
    const float* noninv = (const float*)d_in[1];
    const float* eW1 = (const float*)d_in[2];
    const float* eb1 = (const float*)d_in[3];
    const float* eW2 = (const float*)d_in[4];
    const float* eb2 = (const float*)d_in[5];
    const float* eW3 = (const float*)d_in[6];
    const float* eb3 = (const float*)d_in[7];
    const float* dW1 = (const float*)d_in[8];
    const float* db1 = (const float*)d_in[9];
    const float* dW2 = (const float*)d_in[10];
    const float* db2 = (const float*)d_in[11];
    const float* dW3 = (const float*)d_in[12];
    const float* db3 = (const float*)d_in[13];

    prep_sort_kernel<<<1, 512>>>(eW1, eb1, eW2, eb2);
    prep_rec_kernel<<<4, 128>>>(eW1, eb1, eW2, eb2, eW3, eb3);
    fused_kernel<<<BATCH / 128, 256>>>(invar, noninv,
                                       dW1, db1, dW2, db2, dW3, db3,
                                       (float*)d_out);
}

// round 9
// speedup vs baseline: 1.1318x; 1.0809x over previous
#include <cuda_runtime.h>
#include <cuda_fp16.h>
#include <math.h>

// ============================================================================
// PermInvariantQNN — exact piecewise-linear collapse of the scalar encoder.
// Round 9: ONE merged prep kernel (bitonic + count/scan cell build + records),
//          fused enc+dec kernel at 5 blocks/SM with 8-wide eval batching.
// ============================================================================

#define BATCH     131072
#define NBP_MAX   512
#define NSEG_MAX  512
#define NCELL     4096
#define XLO_F     (-6.0f)
#define STEP_F    (12.0f / 4096.0f)
#define INVSTEP_F (4096.0f / 12.0f)
#define HALFCELLS 2048.0f

__device__ float          g_bp[NBP_MAX];        // sorted breakpoints, +INF padded
__device__ unsigned int   g_rec[NSEG_MAX * 6];  // [xmid f32, 5x half2(s,v)] * (1/64)
__device__ unsigned short g_cell[NCELL];        // low15: upper-bound idx, bit15: dirty

// ----------------------------------------------------------------------------
// Merged prep: 1 block x 512 threads. Sort + cells + records.
// ----------------------------------------------------------------------------
__global__ void prep_kernel(const float* __restrict__ eW1, const float* __restrict__ eb1,
                            const float* __restrict__ eW2, const float* __restrict__ eb2,
                            const float* __restrict__ eW3, const float* __restrict__ eb3)
{
    __shared__ float sa[20], sb1[20], sW2[400], sb2[20], sW3[100], sb3[5];
    __shared__ float s_t[21];
    __shared__ int   s_n1, s_n;
    __shared__ float cand[512];
    __shared__ int   s_cnt[NCELL + 1];          // 16.4 KB
    __shared__ int   s_wsum[16];

    const int tid = threadIdx.x;

    if (tid < 20)  { sa[tid] = eW1[tid]; sb1[tid] = eb1[tid]; sb2[tid] = eb2[tid]; }
    if (tid < 400) sW2[tid] = eW2[tid];
    if (tid < 100) sW3[tid] = eW3[tid];
    if (tid < 5)   sb3[tid] = eb3[tid];
    cand[tid] = INFINITY;
    if (tid == 0) s_n = 0;
    __syncthreads();

    // ---- phase 1: layer-1 breakpoints via warp rank-sort ----
    if (tid < 32) {
        float tj = INFINITY;
        if (tid < 20) {
            float a = sa[tid];
            if (a != 0.0f) {
                float t = -sb1[tid] / a;
                if (isfinite(t)) tj = t;
            }
        }
        int rnk = 0;
        #pragma unroll
        for (int j = 0; j < 32; j++) {
            float u = __shfl_sync(0xFFFFFFFFu, tj, j);
            rnk += (u < tj) || (u == tj && j < tid);
        }
        bool fin = isfinite(tj);
        if (fin) { s_t[rnk] = tj; cand[rnk] = tj; }
        unsigned m = __ballot_sync(0xFFFFFFFFu, fin);
        if (tid == 0) { s_n1 = __popc(m); atomicAdd(&s_n, __popc(m)); }
    }
    __syncthreads();
    const int n1 = s_n1;

    // ---- phase 2: layer-2 zero crossings ----
    if (tid < 21 * 20) {
        int p = tid / 20, k = tid % 20;
        if (p <= n1) {
            float lo = (p == 0)  ? -INFINITY : s_t[p - 1];
            float hi = (p == n1) ?  INFINITY : s_t[p];
            float xr;
            if (n1 == 0)      xr = 0.0f;
            else if (p == 0)  xr = s_t[0] - 1.0f;
            else if (p == n1) xr = s_t[n1 - 1] + 1.0f;
            else              xr = 0.5f * (lo + hi);
            float zs = 0.0f, zi = sb2[k];
            for (int j = 0; j < 20; j++) {
                float pre = fmaf(sa[j], xr, sb1[j]);
                if (pre > 0.0f) {
                    zs = fmaf(sa[j],  sW2[j * 20 + k], zs);
                    zi = fmaf(sb1[j], sW2[j * 20 + k], zi);
                }
            }
            if (zs != 0.0f) {
                float xc = -zi / zs;
                if (isfinite(xc) && xc > lo && xc < hi) {
                    cand[20 + p * 20 + k] = xc;
                    atomicAdd(&s_n, 1);
                }
            }
        }
    }
    __syncthreads();

    // ---- phase 3: hybrid bitonic sort ----
    {
        float v = cand[tid];
        for (int k = 2; k <= 512; k <<= 1) {
            for (int j = k >> 1; j > 0; j >>= 1) {
                float u;
                if (j >= 32) {
                    cand[tid] = v; __syncthreads();
                    u = cand[tid ^ j]; __syncthreads();
                } else {
                    u = __shfl_xor_sync(0xFFFFFFFFu, v, j);
                }
                bool up = ((tid & k) == 0);
                bool keepmin = (up == ((tid & j) == 0));
                v = keepmin ? fminf(v, u) : fmaxf(v, u);
            }
        }
        cand[tid] = v;
        __syncthreads();
    }

    const int n = s_n;
    g_bp[tid] = cand[tid];                       // +INF padded beyond n

    // ---- phase 4: cell table via count + prefix scan ----
    for (int c = tid; c < NCELL + 1; c += 512) s_cnt[c] = 0;
    __syncthreads();

    if (tid < n) {
        float b = cand[tid];
        // c0 = min c with left_c >= b  (clamped to [0, NCELL])
        int c0 = (int)ceilf((b - XLO_F) * INVSTEP_F);
        c0 = min(max(c0, 0), NCELL);
        while (c0 > 0 && XLO_F + (float)(c0 - 1) * STEP_F >= b) c0--;
        while (c0 < NCELL && XLO_F + (float)c0 * STEP_F < b)    c0++;
        atomicAdd(&s_cnt[c0], 1);
    }
    __syncthreads();

    {
        const int base = tid * 8;                // covers 0..4095
        int v[8];
        int run = 0;
        #pragma unroll
        for (int i = 0; i < 8; i++) { run += s_cnt[base + i]; v[i] = run; }

        // block exclusive scan of per-thread sums
        int lane = tid & 31, wrp = tid >> 5;
        int x = run;
        #pragma unroll
        for (int off = 1; off < 32; off <<= 1) {
            int y = __shfl_up_sync(0xFFFFFFFFu, x, off);
            if (lane >= off) x += y;
        }
        if (lane == 31) s_wsum[wrp] = x;
        __syncthreads();
        if (tid == 0) {
            int a = 0;
            #pragma unroll
            for (int w = 0; w < 16; w++) { int t = s_wsum[w]; s_wsum[w] = a; a += t; }
        }
        __syncthreads();
        const int off0 = s_wsum[wrp] + (x - run);   // exclusive prefix of this chunk

        #pragma unroll
        for (int i = 0; i < 8; i++) {
            int S     = off0 + v[i];                      // #bp <= left edge
            int dirty = (s_cnt[base + i + 1] > 0) ? 0x8000 : 0;
            g_cell[base + i] = (unsigned short)(S | dirty);
        }
    }

    // ---- phase 5: per-segment records (threads 0..n), scaled by 1/64 ----
    if (tid <= n) {
        float xr;
        if (n == 0)        xr = 0.0f;
        else if (tid == 0) xr = cand[0] - 1.0f;
        else if (tid == n) xr = cand[n - 1] + 1.0f;
        else               xr = 0.5f * (cand[tid - 1] + cand[tid]);

        float ha[20], hb[20];
        #pragma unroll
        for (int j = 0; j < 20; j++) {
            float pre = fmaf(sa[j], xr, sb1[j]);
            bool act = pre > 0.0f;
            ha[j] = act ? sa[j]  : 0.0f;
            hb[j] = act ? sb1[j] : 0.0f;
        }
        float sm[5] = {0, 0, 0, 0, 0}, cm[5] = {0, 0, 0, 0, 0};
        for (int k = 0; k < 20; k++) {
            float zs = 0.0f, zi = sb2[k];
            #pragma unroll
            for (int j = 0; j < 20; j++) {
                zs = fmaf(ha[j], sW2[j * 20 + k], zs);
                zi = fmaf(hb[j], sW2[j * 20 + k], zi);
            }
            if (fmaf(zs, xr, zi) > 0.0f) {
                #pragma unroll
                for (int m = 0; m < 5; m++) {
                    sm[m] = fmaf(zs, sW3[k * 5 + m], sm[m]);
                    cm[m] = fmaf(zi, sW3[k * 5 + m], cm[m]);
                }
            }
        }
        unsigned int* rec = g_rec + tid * 6;
        rec[0] = __float_as_uint(xr);
        #pragma unroll
        for (int m = 0; m < 5; m++) {
            float v = fmaf(sm[m], xr, cm[m] + sb3[m]);   // f_m at xr
            __half2 h = __floats2half2_rn(sm[m] * 0.015625f, v * 0.015625f);
            rec[1 + m] = *(unsigned int*)&h;
        }
    }
}

// ----------------------------------------------------------------------------
// Fused encoder+decoder: thread-pair per row.
// ----------------------------------------------------------------------------
__device__ __forceinline__ int pwl_find(float x,
                                        const float* __restrict__ s_bp,
                                        const unsigned short* __restrict__ s_cell)
{
    float fc = fmaf(x, INVSTEP_F, HALFCELLS);
    int c = __float2int_rz(fc);
    c = min(max(c, 0), NCELL - 1);
    unsigned e = s_cell[c];
    int s = e & 0x7FFF;
    bool walk = (e & 0x8000u) != 0;
    if (fc < 0.0f) { s = 0; walk = true; }
    if (walk) { while (s_bp[s] <= x) ++s; }      // +INF padding terminates
    return s;
}

__device__ __forceinline__ void pwl_acc(float x, const uint2* __restrict__ p,
                                        float acc[5])
{
    uint2 r0 = p[0], r1 = p[1], r2 = p[2];
    float dx = x - __uint_as_float(r0.x);
    float2 m0 = __half22float2(*(__half2*)&r0.y);
    float2 m1 = __half22float2(*(__half2*)&r1.x);
    float2 m2 = __half22float2(*(__half2*)&r1.y);
    float2 m3 = __half22float2(*(__half2*)&r2.x);
    float2 m4 = __half22float2(*(__half2*)&r2.y);
    acc[0] += fmaf(m0.x, dx, m0.y);
    acc[1] += fmaf(m1.x, dx, m1.y);
    acc[2] += fmaf(m2.x, dx, m2.y);
    acc[3] += fmaf(m3.x, dx, m3.y);
    acc[4] += fmaf(m4.x, dx, m4.y);
}

__global__ __launch_bounds__(256, 5) void fused_kernel(
    const float* __restrict__ inv,  const float* __restrict__ noninv,
    const float* __restrict__ dW1,  const float* __restrict__ db1,
    const float* __restrict__ dW2,  const float* __restrict__ db2,
    const float* __restrict__ dW3,  const float* __restrict__ db3,
    float* __restrict__ out)
{
    __shared__ __align__(16) float          s_bp[NBP_MAX];       // 2 KB
    __shared__ __align__(16) unsigned int   s_rec[NSEG_MAX * 6]; // 12 KB
    __shared__ __align__(16) unsigned short s_cell[NCELL];       // 8 KB
    __shared__ __align__(16) float          s_dw[784];           // 3.1 KB

    const int tid = threadIdx.x;

    {
        const uint4* src = (const uint4*)g_rec;
        uint4* dst = (uint4*)s_rec;
        #pragma unroll
        for (int i = tid; i < NSEG_MAX * 6 / 4; i += 256) dst[i] = src[i];
        ((float2*)s_bp)[tid] = ((const float2*)g_bp)[tid];
        const uint4* csrc = (const uint4*)g_cell;
        uint4* cdst = (uint4*)s_cell;
        #pragma unroll
        for (int i = tid; i < NCELL / 8; i += 256) cdst[i] = csrc[i];
        for (int i = tid; i < 260; i += 256) s_dw[i] = dW1[i];
        if (tid < 20) s_dw[260 + tid] = db1[tid];
        for (int i = tid; i < 400; i += 256) s_dw[280 + i] = dW2[i];
        if (tid < 20) s_dw[680 + tid] = db2[tid];
        if (tid < 80) s_dw[700 + tid] = dW3[tid];
        if (tid < 4)  s_dw[780 + tid] = db3[tid];
    }
    __syncthreads();

    const int gtid = blockIdx.x * 256 + tid;
    const int r    = gtid >> 1;          // row
    const int half = gtid & 1;           // 0/1: input half + neuron half
    const int nb   = half * 10;          // neuron base
    const uint2* rec = (const uint2*)s_rec;

    // -------- encoder: my 32 of the row's 64 inputs, 8 evals in flight --------
    float acc[5] = {0, 0, 0, 0, 0};
    const float4* p0 = (const float4*)inv + (size_t)r * 16 + half * 8;
    #pragma unroll
    for (int i = 0; i < 8; i += 2) {
        float4 a = p0[i];
        float4 b = p0[i + 1];
        int s0 = pwl_find(a.x, s_bp, s_cell);
        int s1 = pwl_find(a.y, s_bp, s_cell);
        int s2 = pwl_find(a.z, s_bp, s_cell);
        int s3 = pwl_find(a.w, s_bp, s_cell);
        int s4 = pwl_find(b.x, s_bp, s_cell);
        int s5 = pwl_find(b.y, s_bp, s_cell);
        int s6 = pwl_find(b.z, s_bp, s_cell);
        int s7 = pwl_find(b.w, s_bp, s_cell);
        pwl_acc(a.x, rec + s0 * 3, acc);
        pwl_acc(a.y, rec + s1 * 3, acc);
        pwl_acc(a.z, rec + s2 * 3, acc);
        pwl_acc(a.w, rec + s3 * 3, acc);
        pwl_acc(b.x, rec + s4 * 3, acc);
        pwl_acc(b.y, rec + s5 * 3, acc);
        pwl_acc(b.z, rec + s6 * 3, acc);
        pwl_acc(b.w, rec + s7 * 3, acc);
    }

    // -------- combine moments across the pair; build cat[13] --------
    float cat[13];
    #pragma unroll
    for (int m = 0; m < 5; m++)
        cat[m] = acc[m] + __shfl_xor_sync(0xFFFFFFFFu, acc[m], 1);
    {
        float4 u0 = *(const float4*)(noninv + (size_t)r * 8);
        float4 u1 = *(const float4*)(noninv + (size_t)r * 8 + 4);
        cat[5] = u0.x; cat[6] = u0.y; cat[7]  = u0.z; cat[8]  = u0.w;
        cat[9] = u1.x; cat[10] = u1.y; cat[11] = u1.z; cat[12] = u1.w;
    }

    // -------- decoder layer 1: my 10 neurons --------
    float myh[10];
    #pragma unroll
    for (int i = 0; i < 10; i += 2) {
        float2 z = *(const float2*)&s_dw[260 + nb + i];
        #pragma unroll
        for (int c = 0; c < 13; c++) {
            float2 w = *(const float2*)&s_dw[c * 20 + nb + i];
            z.x = fmaf(cat[c], w.x, z.x);
            z.y = fmaf(cat[c], w.y, z.y);
        }
        myh[i]     = fmaxf(z.x, 0.0f);
        myh[i + 1] = fmaxf(z.y, 0.0f);
    }

    // -------- exchange h halves --------
    float hall[20];
    #pragma unroll
    for (int i = 0; i < 10; i++) {
        float o = __shfl_xor_sync(0xFFFFFFFFu, myh[i], 1);
        hall[i]      = half ? o      : myh[i];
        hall[10 + i] = half ? myh[i] : o;
    }

    // -------- decoder layer 2: my 10 neurons --------
    float g[10];
    #pragma unroll
    for (int i = 0; i < 10; i += 2) {
        float2 z = *(const float2*)&s_dw[680 + nb + i];
        #pragma unroll
        for (int j = 0; j < 20; j++) {
            float2 w = *(const float2*)&s_dw[280 + j * 20 + nb + i];
            z.x = fmaf(hall[j], w.x, z.x);
            z.y = fmaf(hall[j], w.y, z.y);
        }
        g[i]     = fmaxf(z.x, 0.0f);
        g[i + 1] = fmaxf(z.y, 0.0f);
    }

    // -------- decoder layer 3: partial + shfl reduce --------
    float4 o = half ? make_float4(0.f, 0.f, 0.f, 0.f)
                    : *(const float4*)&s_dw[780];
    #pragma unroll
    for (int i = 0; i < 10; i++) {
        float4 w = *(const float4*)&s_dw[700 + (nb + i) * 4];
        o.x = fmaf(g[i], w.x, o.x);
        o.y = fmaf(g[i], w.y, o.y);
        o.z = fmaf(g[i], w.z, o.z);
        o.w = fmaf(g[i], w.w, o.w);
    }
    o.x += __shfl_xor_sync(0xFFFFFFFFu, o.x, 1);
    o.y += __shfl_xor_sync(0xFFFFFFFFu, o.y, 1);
    o.z += __shfl_xor_sync(0xFFFFFFFFu, o.z, 1);
    o.w += __shfl_xor_sync(0xFFFFFFFFu, o.w, 1);
    if (half == 0)
        *(float4*)(out + (size_t)r * 4) = o;
}

// ----------------------------------------------------------------------------
extern "C" void kernel_launch(void* const* d_in, const int* in_sizes, int n_in,
                              void* d_out, int out_size)
{
    (void)in_sizes; (void)n_in; (void)out_size;
    const float* invar  = (const float*)d_in[0];
    const float* noninv = (const float*)d_in[1];
    const float* eW1 = (const float*)d_in[2];
    const float* eb1 = (const float*)d_in[3];
    const float* eW2 = (const float*)d_in[4];
    const float* eb2 = (const float*)d_in[5];
    const float* eW3 = (const float*)d_in[6];
    const float* eb3 = (const float*)d_in[7];
    const float* dW1 = (const float*)d_in[8];
    const float* db1 = (const float*)d_in[9];
    const float* dW2 = (const float*)d_in[10];
    const float* db2 = (const float*)d_in[11];
    const float* dW3 = (const float*)d_in[12];
    const float* db3 = (const float*)d_in[13];

    prep_kernel<<<1, 512>>>(eW1, eb1, eW2, eb2, eW3, eb3);
    fused_kernel<<<BATCH / 128, 256>>>(invar, noninv,
                                       dW1, db1, dW2, db2, dW3, db3,
                                       (float*)d_out);
}